// round 1
// baseline (speedup 1.0000x reference)
#include <cuda_runtime.h>
#include <math.h>

#define NNODES 2048
#define NEDGES 65536
#define NB     8
#define FMAX   1024
#define NROWS  (NB * NNODES)   // 16384
#define BN_EPS 1e-5f

// ---------------- device scratch (no allocations allowed) ----------------
__device__ int   g_is64;
__device__ int   g_deg[NNODES];
__device__ float g_dinv[NNODES];
__device__ int   g_off[NNODES + 1];
__device__ int   g_cursor[NNODES];
__device__ int   g_csr_src[NEDGES];
__device__ float g_csr_norm[NEDGES];
__device__ float g_alpha[NB * FMAX];
__device__ float g_beta[NB * FMAX];
__device__ float g_P[(size_t)NROWS * FMAX];     // aggregation output (GEMM A)
__device__ float g_T[(size_t)NROWS * FMAX];     // GEMM output (pre-BN, post-leaky)
__device__ float g_Hbuf[(size_t)NROWS * FMAX];  // normalized hidden state

// ---------------- edge dtype detection ----------------
__global__ void detect_kernel(const void* edges) {
    if (threadIdx.x == 0) {
        const long long* p = (const long long*)edges;
        int is64 = 1;
        for (int i = 0; i < 16; i++) {
            long long v = p[i];
            if (v < 0 || v >= NNODES) is64 = 0;
        }
        g_is64 = is64;
    }
}

__device__ __forceinline__ int edge_val(const void* edges, int idx) {
    if (g_is64) return (int)((const long long*)edges)[idx];
    return ((const int*)edges)[idx];
}

// ---------------- graph preprocessing ----------------
__global__ void zero_deg_kernel() {
    int i = blockIdx.x * blockDim.x + threadIdx.x;
    if (i < NNODES) g_deg[i] = 0;
}

__global__ void count_deg_kernel(const void* edges) {
    int e = blockIdx.x * blockDim.x + threadIdx.x;
    if (e < NEDGES) {
        int dst = edge_val(edges, NEDGES + e);
        atomicAdd(&g_deg[dst], 1);
    }
}

__global__ void dinv_kernel() {
    int i = blockIdx.x * blockDim.x + threadIdx.x;
    if (i < NNODES) g_dinv[i] = rsqrtf((float)(g_deg[i] + 1));  // +1 self loop
}

// exclusive scan of g_deg (2048 entries) -> g_off, g_cursor. One block, 1024 thr.
__global__ void scan_kernel() {
    __shared__ int part[1024];
    int t = threadIdx.x;
    int c0 = g_deg[2 * t];
    int c1 = g_deg[2 * t + 1];
    part[t] = c0 + c1;
    __syncthreads();
    for (int off = 1; off < 1024; off <<= 1) {
        int v = (t >= off) ? part[t - off] : 0;
        __syncthreads();
        part[t] += v;
        __syncthreads();
    }
    int base = (t > 0) ? part[t - 1] : 0;
    g_off[2 * t]     = base;
    g_off[2 * t + 1] = base + c0;
    g_cursor[2 * t]     = base;
    g_cursor[2 * t + 1] = base + c0;
    if (t == 1023) g_off[2048] = part[1023];
}

__global__ void fill_kernel(const void* edges) {
    int e = blockIdx.x * blockDim.x + threadIdx.x;
    if (e < NEDGES) {
        int s = edge_val(edges, e);
        int d = edge_val(edges, NEDGES + e);
        int p = atomicAdd(&g_cursor[d], 1);
        g_csr_src[p]  = s;
        g_csr_norm[p] = g_dinv[s] * g_dinv[d];
    }
}

// ---------------- aggregation: P[b][i][:] = sum_in norm*H[b][src][:] + dinv_i^2*H[b][i][:] ----------------
template <int F>
__global__ void agg_kernel(const float* __restrict__ Hsrc, float* __restrict__ P) {
    constexpr int F4 = F / 4;
    int b    = blockIdx.y;
    int node = blockIdx.x * blockDim.y + threadIdx.y;
    int f4   = threadIdx.x;
    const float4* Hb = reinterpret_cast<const float4*>(Hsrc) + (size_t)b * NNODES * F4;

    float wself = g_dinv[node] * g_dinv[node];
    float4 hv = Hb[(size_t)node * F4 + f4];
    float4 acc;
    acc.x = wself * hv.x; acc.y = wself * hv.y; acc.z = wself * hv.z; acc.w = wself * hv.w;

    int beg = g_off[node], end = g_off[node + 1];
    for (int e = beg; e < end; e++) {
        int   s = g_csr_src[e];
        float w = g_csr_norm[e];
        float4 h = Hb[(size_t)s * F4 + f4];
        acc.x += w * h.x; acc.y += w * h.y; acc.z += w * h.z; acc.w += w * h.w;
    }
    reinterpret_cast<float4*>(P)[(size_t)b * NNODES * F4 + (size_t)node * F4 + f4] = acc;
}

// ---------------- fp32 GEMM: C[r][o] = leaky(sum_k A[r,k]*W[o,k] + bias[o]) ----------------
// 128x128 tile, BK=8, 256 threads, 8x8 microtile. M=16384, K,O multiples of 8/128.
__global__ __launch_bounds__(256) void sgemm_kernel(
    const float* __restrict__ A, const float* __restrict__ W,
    const float* __restrict__ bias, float* __restrict__ C, int K, int O) {
    __shared__ __align__(16) float As[8][128];
    __shared__ __align__(16) float Bs[8][128];
    int tid  = threadIdx.x;
    int brow = blockIdx.y * 128;
    int bcol = blockIdx.x * 128;
    int lr = tid >> 1;
    int lc = (tid & 1) * 4;
    const float* Ag = A + (size_t)(brow + lr) * K + lc;
    const float* Wg = W + (size_t)(bcol + lr) * K + lc;
    int tx = tid & 15, ty = tid >> 4;

    float acc[8][8];
#pragma unroll
    for (int i = 0; i < 8; i++)
#pragma unroll
        for (int j = 0; j < 8; j++) acc[i][j] = 0.f;

    for (int k0 = 0; k0 < K; k0 += 8) {
        float4 av = *(const float4*)(Ag + k0);
        float4 wv = *(const float4*)(Wg + k0);
        __syncthreads();
        As[lc + 0][lr] = av.x; As[lc + 1][lr] = av.y; As[lc + 2][lr] = av.z; As[lc + 3][lr] = av.w;
        Bs[lc + 0][lr] = wv.x; Bs[lc + 1][lr] = wv.y; Bs[lc + 2][lr] = wv.z; Bs[lc + 3][lr] = wv.w;
        __syncthreads();
#pragma unroll
        for (int kk = 0; kk < 8; kk++) {
            float4 a0 = *(const float4*)&As[kk][ty * 8];
            float4 a1 = *(const float4*)&As[kk][ty * 8 + 4];
            float4 b0 = *(const float4*)&Bs[kk][tx * 8];
            float4 b1 = *(const float4*)&Bs[kk][tx * 8 + 4];
            float a[8] = {a0.x, a0.y, a0.z, a0.w, a1.x, a1.y, a1.z, a1.w};
            float b[8] = {b0.x, b0.y, b0.z, b0.w, b1.x, b1.y, b1.z, b1.w};
#pragma unroll
            for (int i = 0; i < 8; i++)
#pragma unroll
                for (int j = 0; j < 8; j++) acc[i][j] += a[i] * b[j];
        }
    }

    float4 bz0 = *(const float4*)(bias + bcol + tx * 8);
    float4 bz1 = *(const float4*)(bias + bcol + tx * 8 + 4);
    float bb[8] = {bz0.x, bz0.y, bz0.z, bz0.w, bz1.x, bz1.y, bz1.z, bz1.w};
#pragma unroll
    for (int i = 0; i < 8; i++) {
        size_t row = (size_t)(brow + ty * 8 + i);
        float* Crow = C + row * O + bcol + tx * 8;
        float v[8];
#pragma unroll
        for (int j = 0; j < 8; j++) {
            float u = acc[i][j] + bb[j];
            v[j] = (u > 0.f) ? u : 0.01f * u;   // leaky relu fused
        }
        *(float4*)(Crow)     = make_float4(v[0], v[1], v[2], v[3]);
        *(float4*)(Crow + 4) = make_float4(v[4], v[5], v[6], v[7]);
    }
}

// ---------------- BN stats: per (b, channel) mean/var over nodes -> alpha,beta ----------------
__global__ void stats_kernel(const float* __restrict__ T, const float* __restrict__ g,
                             const float* __restrict__ be, int O) {
    int b = blockIdx.y;
    int o = blockIdx.x * 256 + threadIdx.x;
    if (o >= O) return;
    const float* base = T + (size_t)b * NNODES * O + o;
    float s = 0.f, s2 = 0.f;
    for (int n = 0; n < NNODES; n++) {
        float v = base[(size_t)n * O];
        s += v; s2 += v * v;
    }
    float mu  = s * (1.0f / NNODES);
    float var = s2 * (1.0f / NNODES) - mu * mu;
    if (var < 0.f) var = 0.f;
    float a = g[o] * rsqrtf(var + BN_EPS);
    g_alpha[b * O + o] = a;
    g_beta[b * O + o]  = be[o] - mu * a;
}

// ---------------- apply BN (layers 1-4): H = T*alpha + beta ----------------
__global__ void bn_apply_kernel(const float* __restrict__ T, float* __restrict__ Hn, int O) {
    int o4pern  = O / 4;
    int total4  = NROWS * o4pern;
    for (int idx = blockIdx.x * blockDim.x + threadIdx.x; idx < total4;
         idx += gridDim.x * blockDim.x) {
        int b  = idx / (NNODES * o4pern);
        int o4 = idx % o4pern;
        float4 t = ((const float4*)T)[idx];
        float4 a = ((const float4*)g_alpha)[b * o4pern + o4];
        float4 c = ((const float4*)g_beta)[b * o4pern + o4];
        float4 r;
        r.x = t.x * a.x + c.x; r.y = t.y * a.y + c.y;
        r.z = t.z * a.z + c.z; r.w = t.w * a.w + c.w;
        ((float4*)Hn)[idx] = r;
    }
}

// ---------------- layer 5: BN apply + per-node LayerNorm, write output ----------------
__global__ void final_kernel(const float* __restrict__ T, const float* __restrict__ ln_g,
                             const float* __restrict__ ln_b, float* __restrict__ out) {
    const int O = 1024;
    int b = blockIdx.y, n = blockIdx.x, t = threadIdx.x;  // 256 threads, 4 ch each
    size_t rowbase = ((size_t)b * NNODES + n) * O;
    const float4* Trow = (const float4*)(T + rowbase);
    float4 tv = Trow[t];
    float4 av = ((const float4*)g_alpha)[b * (O / 4) + t];
    float4 cv = ((const float4*)g_beta)[b * (O / 4) + t];
    float4 v;
    v.x = tv.x * av.x + cv.x; v.y = tv.y * av.y + cv.y;
    v.z = tv.z * av.z + cv.z; v.w = tv.w * av.w + cv.w;

    float s  = v.x + v.y + v.z + v.w;
    float s2 = v.x * v.x + v.y * v.y + v.z * v.z + v.w * v.w;
#pragma unroll
    for (int off = 16; off > 0; off >>= 1) {
        s  += __shfl_xor_sync(0xffffffffu, s, off);
        s2 += __shfl_xor_sync(0xffffffffu, s2, off);
    }
    __shared__ float ss[8], ss2[8];
    __shared__ float mu_s, r_s;
    int warp = t >> 5, lane = t & 31;
    if (lane == 0) { ss[warp] = s; ss2[warp] = s2; }
    __syncthreads();
    if (t == 0) {
        float S = 0.f, S2 = 0.f;
        for (int i = 0; i < 8; i++) { S += ss[i]; S2 += ss2[i]; }
        float mu  = S * (1.0f / O);
        float var = S2 * (1.0f / O) - mu * mu;
        if (var < 0.f) var = 0.f;
        mu_s = mu;
        r_s  = rsqrtf(var + BN_EPS);
    }
    __syncthreads();
    float mu = mu_s, r = r_s;
    float4 g4 = ((const float4*)ln_g)[t];
    float4 b4 = ((const float4*)ln_b)[t];
    float4 o;
    o.x = (v.x - mu) * r * g4.x + b4.x;
    o.y = (v.y - mu) * r * g4.y + b4.y;
    o.z = (v.z - mu) * r * g4.z + b4.z;
    o.w = (v.w - mu) * r * g4.w + b4.w;
    ((float4*)(out + rowbase))[t] = o;
}

// ---------------- host ----------------
static void launch_agg(int F, const float* Hc, float* P) {
    if (F == 64)        agg_kernel<64>  <<<dim3(NNODES / 16, NB), dim3(16, 16)>>>(Hc, P);
    else if (F == 256)  agg_kernel<256> <<<dim3(NNODES / 4,  NB), dim3(64, 4)>>>(Hc, P);
    else if (F == 512)  agg_kernel<512> <<<dim3(NNODES / 2,  NB), dim3(128, 2)>>>(Hc, P);
    else                agg_kernel<1024><<<dim3(NNODES,      NB), dim3(256, 1)>>>(Hc, P);
}

extern "C" void kernel_launch(void* const* d_in, const int* in_sizes, int n_in,
                              void* d_out, int out_size) {
    const float *x, *w[5], *bb[5], *gg[5], *be[5], *lng, *lnb;
    const void* edges;
    if (in_sizes[0] == 16384) {
        // setup_inputs dict order: w1,b1,g1,be1, ..., w5,b5,g5,be5, ln_g, ln_b, x, edge_index
        for (int i = 0; i < 5; i++) {
            w[i]  = (const float*)d_in[4 * i + 0];
            bb[i] = (const float*)d_in[4 * i + 1];
            gg[i] = (const float*)d_in[4 * i + 2];
            be[i] = (const float*)d_in[4 * i + 3];
        }
        lng = (const float*)d_in[20];
        lnb = (const float*)d_in[21];
        x   = (const float*)d_in[22];
        edges = d_in[23];
    } else {
        // reference signature order: x, edge_index, w1,b1,g1,be1, ..., ln_g, ln_b
        x     = (const float*)d_in[0];
        edges = d_in[1];
        for (int i = 0; i < 5; i++) {
            w[i]  = (const float*)d_in[2 + 4 * i + 0];
            bb[i] = (const float*)d_in[2 + 4 * i + 1];
            gg[i] = (const float*)d_in[2 + 4 * i + 2];
            be[i] = (const float*)d_in[2 + 4 * i + 3];
        }
        lng = (const float*)d_in[22];
        lnb = (const float*)d_in[23];
    }

    float *P, *T, *Hb;
    cudaGetSymbolAddress((void**)&P,  g_P);
    cudaGetSymbolAddress((void**)&T,  g_T);
    cudaGetSymbolAddress((void**)&Hb, g_Hbuf);

    // graph preprocessing
    detect_kernel<<<1, 32>>>(edges);
    zero_deg_kernel<<<8, 256>>>();
    count_deg_kernel<<<NEDGES / 256, 256>>>(edges);
    dinv_kernel<<<8, 256>>>();
    scan_kernel<<<1, 1024>>>();
    fill_kernel<<<NEDGES / 256, 256>>>(edges);

    const int din[5]  = {64, 256, 512, 1024, 1024};
    const int dout[5] = {256, 512, 1024, 1024, 1024};
    const float* Hc = x;
    for (int l = 0; l < 5; l++) {
        launch_agg(din[l], Hc, P);
        dim3 ggrid(dout[l] / 128, NROWS / 128);
        sgemm_kernel<<<ggrid, 256>>>(P, w[l], bb[l], T, din[l], dout[l]);
        stats_kernel<<<dim3(dout[l] / 256, NB), 256>>>(T, gg[l], be[l], dout[l]);
        if (l < 4) {
            bn_apply_kernel<<<4096, 256>>>(T, Hb, dout[l]);
            Hc = Hb;
        } else {
            final_kernel<<<dim3(NNODES, NB), 256>>>(T, lng, lnb, (float*)d_out);
        }
    }
}

// round 3
// speedup vs baseline: 1.9844x; 1.9844x over previous
#include <cuda_runtime.h>
#include <cuda_bf16.h>
#include <cstdint>
#include <math.h>

#define NNODES 2048
#define NEDGES 65536
#define NB     8
#define FMAX   1024
#define NROWS  (NB * NNODES)   // 16384
#define BN_EPS 1e-5f

// ==================== device scratch ====================
__device__ int   g_is64;
__device__ int   g_deg[NNODES];
__device__ float g_dinv[NNODES];
__device__ int   g_off[NNODES + 1];
__device__ int   g_cursor[NNODES];
__device__ int   g_csr_src[NEDGES];
__device__ float g_csr_norm[NEDGES];
__device__ float g_alpha[NB * FMAX];
__device__ float g_beta[NB * FMAX];
__device__ float g_sum[NB * FMAX];
__device__ float g_sum2[NB * FMAX];
__device__ __align__(16) __nv_bfloat16 g_Phi[(size_t)NROWS * FMAX];
__device__ __align__(16) __nv_bfloat16 g_Plo[(size_t)NROWS * FMAX];
__device__ __align__(16) __nv_bfloat16 g_Whi[FMAX * FMAX];
__device__ __align__(16) __nv_bfloat16 g_Wlo[FMAX * FMAX];
__device__ float g_T[(size_t)NROWS * FMAX];

// ==================== graph preprocessing ====================
__global__ void detect_kernel(const void* edges) {
    if (threadIdx.x == 0) {
        const long long* p = (const long long*)edges;
        int is64 = 1;
        for (int i = 0; i < 16; i++) {
            long long v = p[i];
            if (v < 0 || v >= NNODES) is64 = 0;
        }
        g_is64 = is64;
    }
}
__device__ __forceinline__ int edge_val(const void* edges, int idx) {
    if (g_is64) return (int)((const long long*)edges)[idx];
    return ((const int*)edges)[idx];
}
__global__ void zero_deg_kernel() {
    int i = blockIdx.x * blockDim.x + threadIdx.x;
    if (i < NNODES) g_deg[i] = 0;
}
__global__ void count_deg_kernel(const void* edges) {
    int e = blockIdx.x * blockDim.x + threadIdx.x;
    if (e < NEDGES) atomicAdd(&g_deg[edge_val(edges, NEDGES + e)], 1);
}
__global__ void dinv_kernel() {
    int i = blockIdx.x * blockDim.x + threadIdx.x;
    if (i < NNODES) g_dinv[i] = rsqrtf((float)(g_deg[i] + 1));
}
__global__ void scan_kernel() {
    __shared__ int part[1024];
    int t = threadIdx.x;
    int c0 = g_deg[2 * t];
    int c1 = g_deg[2 * t + 1];
    part[t] = c0 + c1;
    __syncthreads();
    for (int off = 1; off < 1024; off <<= 1) {
        int v = (t >= off) ? part[t - off] : 0;
        __syncthreads();
        part[t] += v;
        __syncthreads();
    }
    int base = (t > 0) ? part[t - 1] : 0;
    g_off[2 * t] = base;        g_off[2 * t + 1] = base + c0;
    g_cursor[2 * t] = base;     g_cursor[2 * t + 1] = base + c0;
    if (t == 1023) g_off[2048] = part[1023];
}
__global__ void fill_kernel(const void* edges) {
    int e = blockIdx.x * blockDim.x + threadIdx.x;
    if (e < NEDGES) {
        int s = edge_val(edges, e);
        int d = edge_val(edges, NEDGES + e);
        int p = atomicAdd(&g_cursor[d], 1);
        g_csr_src[p]  = s;
        g_csr_norm[p] = g_dinv[s] * g_dinv[d];
    }
}

// ==================== aggregation (+fused BN affine) -> hi/lo bf16 ====================
__device__ __forceinline__ uint32_t pack2(float a, float b) {
    __nv_bfloat162 p;
    p.x = __float2bfloat16(a); p.y = __float2bfloat16(b);
    return *(uint32_t*)&p;
}
template <int F, bool BN>
__global__ void agg_kernel(const float* __restrict__ Hsrc,
                           __nv_bfloat16* __restrict__ Phi, __nv_bfloat16* __restrict__ Plo) {
    constexpr int F4 = F / 4;
    int b    = blockIdx.y;
    int node = blockIdx.x * blockDim.y + threadIdx.y;
    int f4   = threadIdx.x;
    const float4* Hb = reinterpret_cast<const float4*>(Hsrc) + (size_t)b * NNODES * F4;

    float4 al, bt;
    if (BN) {
        al = ((const float4*)g_alpha)[b * F4 + f4];
        bt = ((const float4*)g_beta)[b * F4 + f4];
    }
    float wself = g_dinv[node] * g_dinv[node];
    float4 hv = Hb[(size_t)node * F4 + f4];
    if (BN) {
        hv.x = hv.x * al.x + bt.x; hv.y = hv.y * al.y + bt.y;
        hv.z = hv.z * al.z + bt.z; hv.w = hv.w * al.w + bt.w;
    }
    float4 acc;
    acc.x = wself * hv.x; acc.y = wself * hv.y; acc.z = wself * hv.z; acc.w = wself * hv.w;

    int beg = g_off[node], end = g_off[node + 1];
    for (int e = beg; e < end; e++) {
        int   s = g_csr_src[e];
        float w = g_csr_norm[e];
        float4 h = Hb[(size_t)s * F4 + f4];
        if (BN) {
            h.x = h.x * al.x + bt.x; h.y = h.y * al.y + bt.y;
            h.z = h.z * al.z + bt.z; h.w = h.w * al.w + bt.w;
        }
        acc.x += w * h.x; acc.y += w * h.y; acc.z += w * h.z; acc.w += w * h.w;
    }
    float hx = __bfloat162float(__float2bfloat16(acc.x));
    float hy = __bfloat162float(__float2bfloat16(acc.y));
    float hz = __bfloat162float(__float2bfloat16(acc.z));
    float hw = __bfloat162float(__float2bfloat16(acc.w));
    uint2 vhi = make_uint2(pack2(acc.x, acc.y), pack2(acc.z, acc.w));
    uint2 vlo = make_uint2(pack2(acc.x - hx, acc.y - hy), pack2(acc.z - hz, acc.w - hw));
    size_t idx = ((size_t)b * NNODES + node) * F4 + f4;
    ((uint2*)Phi)[idx] = vhi;
    ((uint2*)Plo)[idx] = vlo;
}

// ==================== W fp32 -> hi/lo bf16 ====================
__global__ void convert_w_kernel(const float* __restrict__ w, int n4) {
    int i = blockIdx.x * blockDim.x + threadIdx.x;
    if (i >= n4) return;
    float4 v = ((const float4*)w)[i];
    float hx = __bfloat162float(__float2bfloat16(v.x));
    float hy = __bfloat162float(__float2bfloat16(v.y));
    float hz = __bfloat162float(__float2bfloat16(v.z));
    float hw = __bfloat162float(__float2bfloat16(v.w));
    ((uint2*)g_Whi)[i] = make_uint2(pack2(v.x, v.y), pack2(v.z, v.w));
    ((uint2*)g_Wlo)[i] = make_uint2(pack2(v.x - hx, v.y - hy), pack2(v.z - hz, v.w - hw));
}

// ==================== mma.sync GEMM ====================
// C[16384,O] = leaky(A[16384,K] W[O,K]^T + bias), bf16x3 (AhBh + AlBh + AhBl), fp32 accum.
// CTA tile 128x128, K-step 32, 256 threads = 8 warps (2x4), warp tile 64x32.
#define TK        32
#define SM_STRIDE 80                      // bytes per SMEM row (32 bf16 + 16B pad)
#define MAT_BYTES (128 * SM_STRIDE)       // 10240 per matrix tile
#define STAGE_BYTES (4 * MAT_BYTES)       // Ahi, Alo, Bhi, Blo = 40960
#define GEMM_SMEM (2 * STAGE_BYTES)       // 81920

__device__ __forceinline__ void cp_async16(uint32_t saddr, const void* gptr) {
    asm volatile("cp.async.cg.shared.global [%0], [%1], 16;" :: "r"(saddr), "l"(gptr));
}
__device__ __forceinline__ void cp_commit() { asm volatile("cp.async.commit_group;"); }
__device__ __forceinline__ void ldm_x4(uint32_t* r, uint32_t addr) {
    asm volatile("ldmatrix.sync.aligned.m8n8.x4.shared.b16 {%0,%1,%2,%3}, [%4];"
        : "=r"(r[0]), "=r"(r[1]), "=r"(r[2]), "=r"(r[3]) : "r"(addr));
}
__device__ __forceinline__ void mma16816(float* c, const uint32_t* a, const uint32_t* b) {
    asm volatile("mma.sync.aligned.m16n8k16.row.col.f32.bf16.bf16.f32 "
        "{%0,%1,%2,%3}, {%4,%5,%6,%7}, {%8,%9}, {%0,%1,%2,%3};"
        : "+f"(c[0]), "+f"(c[1]), "+f"(c[2]), "+f"(c[3])
        : "r"(a[0]), "r"(a[1]), "r"(a[2]), "r"(a[3]), "r"(b[0]), "r"(b[1]));
}
__device__ __forceinline__ uint32_t smem_u32(const void* p) {
    uint32_t a;
    asm("{ .reg .u64 t; cvta.to.shared.u64 t, %1; cvt.u32.u64 %0, t; }" : "=r"(a) : "l"(p));
    return a;
}

__global__ __launch_bounds__(256, 1) void mma_gemm_kernel(
    const __nv_bfloat16* __restrict__ Ahi, const __nv_bfloat16* __restrict__ Alo,
    const __nv_bfloat16* __restrict__ Bhi, const __nv_bfloat16* __restrict__ Blo,
    const float* __restrict__ bias, float* __restrict__ C, int K, int O) {
    extern __shared__ __align__(16) char smem[];
    uint32_t sb = smem_u32(smem);
    int tid  = threadIdx.x;
    int lane = tid & 31, wid = tid >> 5;
    int wm = wid >> 2, wn = wid & 3;           // warp grid 2 x 4
    int brow = blockIdx.y * 128;
    int bcol = blockIdx.x * 128;

    float acc[4][16];
#pragma unroll
    for (int i = 0; i < 4; i++)
#pragma unroll
        for (int j = 0; j < 16; j++) acc[i][j] = 0.f;

    // cp.async load of one stage
    const int NC = K / TK;
    auto load_stage = [&](int i) {
        int kc = i * TK;
        uint32_t st = sb + (i & 1) * STAGE_BYTES;
#pragma unroll
        for (int c = 0; c < 2; c++) {
            int idx = tid + 256 * c;            // 0..511
            int row = idx >> 2, q = idx & 3;
            uint32_t soff = (uint32_t)(row * SM_STRIDE + q * 16);
            size_t gA = (size_t)(brow + row) * K + kc + q * 8;
            size_t gB = (size_t)(bcol + row) * K + kc + q * 8;
            cp_async16(st + soff,                 Ahi + gA);
            cp_async16(st + MAT_BYTES + soff,     Alo + gA);
            cp_async16(st + 2 * MAT_BYTES + soff, Bhi + gB);
            cp_async16(st + 3 * MAT_BYTES + soff, Blo + gB);
        }
        cp_commit();
    };

    // per-thread ldmatrix base offsets
    int grp = lane >> 3, l7 = lane & 7;
    // A: matrices (m0-7,k0),(m8-15,k0),(m0-7,k8),(m8-15,k8)
    uint32_t aRow  = (uint32_t)(wm * 64 + (grp & 1) * 8 + l7);
    uint32_t aColB = (uint32_t)((grp >> 1) * 16);
    uint32_t aOff  = aRow * SM_STRIDE + aColB;
    // B: matrices (n0-7,k0),(n0-7,k8),(n8-15,k0),(n8-15,k8)
    uint32_t bRow  = (uint32_t)(wn * 32 + (grp >> 1) * 8 + l7);
    uint32_t bColB = (uint32_t)((grp & 1) * 16);
    uint32_t bOff  = bRow * SM_STRIDE + bColB;

    load_stage(0);
    for (int i = 0; i < NC; i++) {
        if (i + 1 < NC) {
            load_stage(i + 1);
            asm volatile("cp.async.wait_group 1;");
        } else {
            asm volatile("cp.async.wait_group 0;");
        }
        __syncthreads();
        uint32_t st = sb + (i & 1) * STAGE_BYTES;
#pragma unroll
        for (int ks = 0; ks < 2; ks++) {
            uint32_t ah[4][4], al[4][4], bh[2][4], bl[2][4];
#pragma unroll
            for (int mt = 0; mt < 4; mt++) {
                uint32_t a = st + aOff + (uint32_t)(mt * 16 * SM_STRIDE + ks * 32);
                ldm_x4(ah[mt], a);
                ldm_x4(al[mt], a + MAT_BYTES);
            }
#pragma unroll
            for (int np = 0; np < 2; np++) {
                uint32_t b = st + 2 * MAT_BYTES + bOff + (uint32_t)(np * 16 * SM_STRIDE + ks * 32);
                ldm_x4(bh[np], b);
                ldm_x4(bl[np], b + MAT_BYTES);
            }
#pragma unroll
            for (int mt = 0; mt < 4; mt++)
#pragma unroll
                for (int nt = 0; nt < 4; nt++) {
                    float* cc = &acc[mt][nt * 4];
                    const uint32_t* bhf = &bh[nt >> 1][(nt & 1) * 2];
                    const uint32_t* blf = &bl[nt >> 1][(nt & 1) * 2];
                    mma16816(cc, ah[mt], bhf);
                    mma16816(cc, al[mt], bhf);
                    mma16816(cc, ah[mt], blf);
                }
        }
        __syncthreads();
    }

    // epilogue: bias + leaky, direct global stores
    int r0base = brow + wm * 64 + (lane >> 2);
    int cbase  = bcol + wn * 32 + (lane & 3) * 2;
#pragma unroll
    for (int mt = 0; mt < 4; mt++) {
#pragma unroll
        for (int nt = 0; nt < 4; nt++) {
            int c  = cbase + nt * 8;
            float2 bz = *(const float2*)(bias + c);
            float* a4 = &acc[mt][nt * 4];
            float v0 = a4[0] + bz.x, v1 = a4[1] + bz.y;
            float v2 = a4[2] + bz.x, v3 = a4[3] + bz.y;
            v0 = (v0 > 0.f) ? v0 : 0.01f * v0;
            v1 = (v1 > 0.f) ? v1 : 0.01f * v1;
            v2 = (v2 > 0.f) ? v2 : 0.01f * v2;
            v3 = (v3 > 0.f) ? v3 : 0.01f * v3;
            int r0 = r0base + mt * 16;
            *(float2*)(C + (size_t)r0 * O + c)       = make_float2(v0, v1);
            *(float2*)(C + (size_t)(r0 + 8) * O + c) = make_float2(v2, v3);
        }
    }
}

// ==================== BN stats ====================
__global__ void zero_stats_kernel(int O) {
    int i = blockIdx.x * blockDim.x + threadIdx.x;
    if (i < NB * O) { g_sum[i] = 0.f; g_sum2[i] = 0.f; }
}
__global__ void stats_partial_kernel(const float* __restrict__ T, int O) {
    int b = blockIdx.y, z = blockIdx.z;
    int o = blockIdx.x * 256 + threadIdx.x;
    const float* base = T + ((size_t)b * NNODES + z * 256) * O + o;
    float s = 0.f, s2 = 0.f;
#pragma unroll 4
    for (int n = 0; n < 256; n++) {
        float v = base[(size_t)n * O];
        s += v; s2 += v * v;
    }
    atomicAdd(&g_sum[b * O + o], s);
    atomicAdd(&g_sum2[b * O + o], s2);
}
__global__ void stats_final_kernel(const float* __restrict__ g, const float* __restrict__ be, int O) {
    int b = blockIdx.y;
    int o = blockIdx.x * 256 + threadIdx.x;
    float mu  = g_sum[b * O + o] * (1.0f / NNODES);
    float var = g_sum2[b * O + o] * (1.0f / NNODES) - mu * mu;
    if (var < 0.f) var = 0.f;
    float a = g[o] * rsqrtf(var + BN_EPS);
    g_alpha[b * O + o] = a;
    g_beta[b * O + o]  = be[o] - mu * a;
}

// ==================== final: BN apply + LayerNorm ====================
__global__ void final_kernel(const float* __restrict__ T, const float* __restrict__ ln_g,
                             const float* __restrict__ ln_b, float* __restrict__ out) {
    const int O = 1024;
    int b = blockIdx.y, n = blockIdx.x, t = threadIdx.x;
    size_t rowbase = ((size_t)b * NNODES + n) * O;
    float4 tv = ((const float4*)(T + rowbase))[t];
    float4 av = ((const float4*)g_alpha)[b * (O / 4) + t];
    float4 cv = ((const float4*)g_beta)[b * (O / 4) + t];
    float4 v;
    v.x = tv.x * av.x + cv.x; v.y = tv.y * av.y + cv.y;
    v.z = tv.z * av.z + cv.z; v.w = tv.w * av.w + cv.w;

    float s  = v.x + v.y + v.z + v.w;
    float s2 = v.x * v.x + v.y * v.y + v.z * v.z + v.w * v.w;
#pragma unroll
    for (int off = 16; off > 0; off >>= 1) {
        s  += __shfl_xor_sync(0xffffffffu, s, off);
        s2 += __shfl_xor_sync(0xffffffffu, s2, off);
    }
    __shared__ float ss[8], ss2[8];
    __shared__ float mu_s, r_s;
    int warp = t >> 5, lane = t & 31;
    if (lane == 0) { ss[warp] = s; ss2[warp] = s2; }
    __syncthreads();
    if (t == 0) {
        float S = 0.f, S2 = 0.f;
        for (int i = 0; i < 8; i++) { S += ss[i]; S2 += ss2[i]; }
        float mu  = S * (1.0f / O);
        float var = S2 * (1.0f / O) - mu * mu;
        if (var < 0.f) var = 0.f;
        mu_s = mu;
        r_s  = rsqrtf(var + BN_EPS);
    }
    __syncthreads();
    float mu = mu_s, r = r_s;
    float4 g4 = ((const float4*)ln_g)[t];
    float4 b4 = ((const float4*)ln_b)[t];
    float4 o;
    o.x = (v.x - mu) * r * g4.x + b4.x;
    o.y = (v.y - mu) * r * g4.y + b4.y;
    o.z = (v.z - mu) * r * g4.z + b4.z;
    o.w = (v.w - mu) * r * g4.w + b4.w;
    ((float4*)(out + rowbase))[t] = o;
}

// ==================== host ====================
static void launch_agg(int F, bool bn, const float* Hc, __nv_bfloat16* Phi, __nv_bfloat16* Plo) {
    if (F == 64)        agg_kernel<64, false>  <<<dim3(NNODES / 16, NB), dim3(16, 16)>>>(Hc, Phi, Plo);
    else if (F == 256)  agg_kernel<256, true>  <<<dim3(NNODES / 4,  NB), dim3(64, 4)>>>(Hc, Phi, Plo);
    else if (F == 512)  agg_kernel<512, true>  <<<dim3(NNODES / 2,  NB), dim3(128, 2)>>>(Hc, Phi, Plo);
    else                agg_kernel<1024, true> <<<dim3(NNODES,      NB), dim3(256, 1)>>>(Hc, Phi, Plo);
}

extern "C" void kernel_launch(void* const* d_in, const int* in_sizes, int n_in,
                              void* d_out, int out_size) {
    const float *x, *w[5], *bb[5], *gg[5], *be[5], *lng, *lnb;
    const void* edges;
    if (in_sizes[0] == 16384) {
        for (int i = 0; i < 5; i++) {
            w[i]  = (const float*)d_in[4 * i + 0];
            bb[i] = (const float*)d_in[4 * i + 1];
            gg[i] = (const float*)d_in[4 * i + 2];
            be[i] = (const float*)d_in[4 * i + 3];
        }
        lng = (const float*)d_in[20];
        lnb = (const float*)d_in[21];
        x   = (const float*)d_in[22];
        edges = d_in[23];
    } else {
        x     = (const float*)d_in[0];
        edges = d_in[1];
        for (int i = 0; i < 5; i++) {
            w[i]  = (const float*)d_in[2 + 4 * i + 0];
            bb[i] = (const float*)d_in[2 + 4 * i + 1];
            gg[i] = (const float*)d_in[2 + 4 * i + 2];
            be[i] = (const float*)d_in[2 + 4 * i + 3];
        }
        lng = (const float*)d_in[22];
        lnb = (const float*)d_in[23];
    }

    static int smem_set = 0;
    if (!smem_set) {
        cudaFuncSetAttribute(mma_gemm_kernel, cudaFuncAttributeMaxDynamicSharedMemorySize, GEMM_SMEM);
        smem_set = 1;
    }

    __nv_bfloat16 *Phi, *Plo, *Whi, *Wlo;
    float* T;
    cudaGetSymbolAddress((void**)&Phi, g_Phi);
    cudaGetSymbolAddress((void**)&Plo, g_Plo);
    cudaGetSymbolAddress((void**)&Whi, g_Whi);
    cudaGetSymbolAddress((void**)&Wlo, g_Wlo);
    cudaGetSymbolAddress((void**)&T,   g_T);

    detect_kernel<<<1, 32>>>(edges);
    zero_deg_kernel<<<8, 256>>>();
    count_deg_kernel<<<NEDGES / 256, 256>>>(edges);
    dinv_kernel<<<8, 256>>>();
    scan_kernel<<<1, 1024>>>();
    fill_kernel<<<NEDGES / 256, 256>>>(edges);

    const int din[5]  = {64, 256, 512, 1024, 1024};
    const int dout[5] = {256, 512, 1024, 1024, 1024};
    const float* Hc = x;
    for (int l = 0; l < 5; l++) {
        int K = din[l], O = dout[l];
        launch_agg(K, l > 0, Hc, Phi, Plo);
        convert_w_kernel<<<(O * K / 4 + 255) / 256, 256>>>(w[l], O * K / 4);
        mma_gemm_kernel<<<dim3(O / 128, NROWS / 128), 256, GEMM_SMEM>>>(
            Phi, Plo, Whi, Wlo, bb[l], T, K, O);
        zero_stats_kernel<<<(NB * O + 255) / 256, 256>>>(O);
        stats_partial_kernel<<<dim3(O / 256, NB, 8), 256>>>(T, O);
        stats_final_kernel<<<dim3(O / 256, NB), 256>>>(gg[l], be[l], O);
        if (l == 4) final_kernel<<<dim3(NNODES, NB), 256>>>(T, lng, lnb, (float*)d_out);
        Hc = T;
    }
}

// round 4
// speedup vs baseline: 2.2889x; 1.1534x over previous
#include <cuda_runtime.h>
#include <cuda_bf16.h>
#include <cstdint>
#include <math.h>

#define NNODES 2048
#define NEDGES 65536
#define NB     8
#define FMAX   1024
#define NROWS  (NB * NNODES)   // 16384
#define BN_EPS 1e-5f

// ==================== device scratch ====================
__device__ int   g_is64;
__device__ int   g_deg[NNODES];
__device__ float g_dinv[NNODES];
__device__ int   g_off[NNODES + 1];
__device__ int   g_cursor[NNODES];
__device__ int   g_csr_src[NEDGES];
__device__ float g_csr_norm[NEDGES];
__device__ float g_alpha[NB * FMAX];
__device__ float g_beta[NB * FMAX];
__device__ float g_sum[NB * FMAX];    // indexed b*FMAX + o
__device__ float g_sum2[NB * FMAX];
__device__ __align__(16) __nv_bfloat16 g_Phi[(size_t)NROWS * FMAX];
__device__ __align__(16) __nv_bfloat16 g_Plo[(size_t)NROWS * FMAX];
#define WTOTAL 2768896   // sum of all 5 weight matrices
__device__ __align__(16) __nv_bfloat16 g_Whi[WTOTAL];
__device__ __align__(16) __nv_bfloat16 g_Wlo[WTOTAL];
__device__ float g_T[(size_t)NROWS * FMAX];

// ==================== graph preprocessing ====================
__global__ void detect_kernel(const void* edges) {
    if (threadIdx.x == 0) {
        const long long* p = (const long long*)edges;
        int is64 = 1;
        for (int i = 0; i < 16; i++) {
            long long v = p[i];
            if (v < 0 || v >= NNODES) is64 = 0;
        }
        g_is64 = is64;
    }
}
__device__ __forceinline__ int edge_val(const void* edges, int idx) {
    if (g_is64) return (int)((const long long*)edges)[idx];
    return ((const int*)edges)[idx];
}
__global__ void zero_deg_kernel() {
    int i = blockIdx.x * blockDim.x + threadIdx.x;
    if (i < NNODES) g_deg[i] = 0;
}
__global__ void count_deg_kernel(const void* edges) {
    int e = blockIdx.x * blockDim.x + threadIdx.x;
    if (e < NEDGES) atomicAdd(&g_deg[edge_val(edges, NEDGES + e)], 1);
}
__global__ void dinv_kernel() {
    int i = blockIdx.x * blockDim.x + threadIdx.x;
    if (i < NNODES) g_dinv[i] = rsqrtf((float)(g_deg[i] + 1));
}
__global__ void scan_kernel() {
    __shared__ int part[1024];
    int t = threadIdx.x;
    int c0 = g_deg[2 * t];
    int c1 = g_deg[2 * t + 1];
    part[t] = c0 + c1;
    __syncthreads();
    for (int off = 1; off < 1024; off <<= 1) {
        int v = (t >= off) ? part[t - off] : 0;
        __syncthreads();
        part[t] += v;
        __syncthreads();
    }
    int base = (t > 0) ? part[t - 1] : 0;
    g_off[2 * t] = base;        g_off[2 * t + 1] = base + c0;
    g_cursor[2 * t] = base;     g_cursor[2 * t + 1] = base + c0;
    if (t == 1023) g_off[2048] = part[1023];
}
__global__ void fill_kernel(const void* edges) {
    int e = blockIdx.x * blockDim.x + threadIdx.x;
    if (e < NEDGES) {
        int s = edge_val(edges, e);
        int d = edge_val(edges, NEDGES + e);
        int p = atomicAdd(&g_cursor[d], 1);
        g_csr_src[p]  = s;
        g_csr_norm[p] = g_dinv[s] * g_dinv[d];
    }
}

// ==================== weight conversion (all 5 layers, one launch) ====================
__device__ __forceinline__ uint32_t pack2(float a, float b) {
    __nv_bfloat162 p;
    p.x = __float2bfloat16(a); p.y = __float2bfloat16(b);
    return *(uint32_t*)&p;
}
// element offsets of each layer's weights inside g_Whi/g_Wlo
__constant__ int c_woff4[6] = {0, 4096, 36864, 167936, 430080, 692224}; // in float4 units
__global__ void convert_all_w_kernel(const float* __restrict__ w1, const float* __restrict__ w2,
                                     const float* __restrict__ w3, const float* __restrict__ w4,
                                     const float* __restrict__ w5) {
    int i = blockIdx.x * blockDim.x + threadIdx.x;
    if (i >= 692224) return;
    const float* src;
    int local;
    if (i < c_woff4[1])      { src = w1; local = i; }
    else if (i < c_woff4[2]) { src = w2; local = i - c_woff4[1]; }
    else if (i < c_woff4[3]) { src = w3; local = i - c_woff4[2]; }
    else if (i < c_woff4[4]) { src = w4; local = i - c_woff4[3]; }
    else                     { src = w5; local = i - c_woff4[4]; }
    float4 v = ((const float4*)src)[local];
    float hx = __bfloat162float(__float2bfloat16(v.x));
    float hy = __bfloat162float(__float2bfloat16(v.y));
    float hz = __bfloat162float(__float2bfloat16(v.z));
    float hw = __bfloat162float(__float2bfloat16(v.w));
    ((uint2*)g_Whi)[i] = make_uint2(pack2(v.x, v.y), pack2(v.z, v.w));
    ((uint2*)g_Wlo)[i] = make_uint2(pack2(v.x - hx, v.y - hy), pack2(v.z - hz, v.w - hw));
}

// ==================== aggregation (raw gather + deferred BN affine) -> hi/lo bf16 ====================
template <int F, bool BN>
__global__ void agg_kernel(const float* __restrict__ Hsrc,
                           __nv_bfloat16* __restrict__ Phi, __nv_bfloat16* __restrict__ Plo) {
    constexpr int F4 = F / 4;
    int b = blockIdx.y;
    // zero BN-stat accumulators for THIS layer's GEMM (runs before GEMM in-stream)
    if (blockIdx.x == 0) {
        int ft = threadIdx.y * blockDim.x + threadIdx.x;
        for (int i = ft; i < FMAX; i += 256) {
            g_sum[b * FMAX + i]  = 0.f;
            g_sum2[b * FMAX + i] = 0.f;
        }
    }
    int node = blockIdx.x * blockDim.y + threadIdx.y;
    int f4   = threadIdx.x;
    const float4* Hb = reinterpret_cast<const float4*>(Hsrc) + (size_t)b * NNODES * F4;

    float wself = g_dinv[node] * g_dinv[node];
    float4 hv = Hb[(size_t)node * F4 + f4];
    float4 acc = make_float4(wself * hv.x, wself * hv.y, wself * hv.z, wself * hv.w);
    float4 acc2 = make_float4(0.f, 0.f, 0.f, 0.f);
    float wsum = wself, wsum2 = 0.f;

    int beg = g_off[node], end = g_off[node + 1];
    int e = beg;
    for (; e + 2 <= end; e += 2) {
        int   s0 = g_csr_src[e],     s1 = g_csr_src[e + 1];
        float w0 = g_csr_norm[e],    w1 = g_csr_norm[e + 1];
        float4 h0 = Hb[(size_t)s0 * F4 + f4];
        float4 h1 = Hb[(size_t)s1 * F4 + f4];
        acc.x  += w0 * h0.x; acc.y  += w0 * h0.y; acc.z  += w0 * h0.z; acc.w  += w0 * h0.w;
        acc2.x += w1 * h1.x; acc2.y += w1 * h1.y; acc2.z += w1 * h1.z; acc2.w += w1 * h1.w;
        wsum += w0; wsum2 += w1;
    }
    if (e < end) {
        int   s = g_csr_src[e];
        float w = g_csr_norm[e];
        float4 h = Hb[(size_t)s * F4 + f4];
        acc.x += w * h.x; acc.y += w * h.y; acc.z += w * h.z; acc.w += w * h.w;
        wsum += w;
    }
    acc.x += acc2.x; acc.y += acc2.y; acc.z += acc2.z; acc.w += acc2.w;
    wsum += wsum2;

    if (BN) {
        float4 al = ((const float4*)g_alpha)[b * F4 + f4];
        float4 bt = ((const float4*)g_beta)[b * F4 + f4];
        acc.x = acc.x * al.x + bt.x * wsum;
        acc.y = acc.y * al.y + bt.y * wsum;
        acc.z = acc.z * al.z + bt.z * wsum;
        acc.w = acc.w * al.w + bt.w * wsum;
    }
    float hx = __bfloat162float(__float2bfloat16(acc.x));
    float hy = __bfloat162float(__float2bfloat16(acc.y));
    float hz = __bfloat162float(__float2bfloat16(acc.z));
    float hw = __bfloat162float(__float2bfloat16(acc.w));
    size_t idx = ((size_t)b * NNODES + node) * F4 + f4;
    ((uint2*)Phi)[idx] = make_uint2(pack2(acc.x, acc.y), pack2(acc.z, acc.w));
    ((uint2*)Plo)[idx] = make_uint2(pack2(acc.x - hx, acc.y - hy), pack2(acc.z - hz, acc.w - hw));
}

// ==================== mma.sync GEMM (3-stage pipeline, fused BN stats) ====================
#define TK        32
#define SM_STRIDE 80
#define MAT_BYTES (128 * SM_STRIDE)       // 10240
#define STAGE_BYTES (4 * MAT_BYTES)       // 40960
#define GEMM_SMEM (3 * STAGE_BYTES)       // 122880

__device__ __forceinline__ void cp_async16(uint32_t saddr, const void* gptr) {
    asm volatile("cp.async.cg.shared.global [%0], [%1], 16;" :: "r"(saddr), "l"(gptr));
}
__device__ __forceinline__ void ldm_x4(uint32_t* r, uint32_t addr) {
    asm volatile("ldmatrix.sync.aligned.m8n8.x4.shared.b16 {%0,%1,%2,%3}, [%4];"
        : "=r"(r[0]), "=r"(r[1]), "=r"(r[2]), "=r"(r[3]) : "r"(addr));
}
__device__ __forceinline__ void mma16816(float* c, const uint32_t* a, const uint32_t* b) {
    asm volatile("mma.sync.aligned.m16n8k16.row.col.f32.bf16.bf16.f32 "
        "{%0,%1,%2,%3}, {%4,%5,%6,%7}, {%8,%9}, {%0,%1,%2,%3};"
        : "+f"(c[0]), "+f"(c[1]), "+f"(c[2]), "+f"(c[3])
        : "r"(a[0]), "r"(a[1]), "r"(a[2]), "r"(a[3]), "r"(b[0]), "r"(b[1]));
}
__device__ __forceinline__ uint32_t smem_u32(const void* p) {
    uint32_t a;
    asm("{ .reg .u64 t; cvta.to.shared.u64 t, %1; cvt.u32.u64 %0, t; }" : "=r"(a) : "l"(p));
    return a;
}

__global__ __launch_bounds__(256, 1) void mma_gemm_kernel(
    const __nv_bfloat16* __restrict__ Ahi, const __nv_bfloat16* __restrict__ Alo,
    const __nv_bfloat16* __restrict__ Bhi, const __nv_bfloat16* __restrict__ Blo,
    const float* __restrict__ bias, float* __restrict__ C, int K, int O) {
    extern __shared__ __align__(16) char smem[];
    uint32_t sb = smem_u32(smem);
    int tid  = threadIdx.x;
    int lane = tid & 31, wid = tid >> 5;
    int wm = wid >> 2, wn = wid & 3;
    int brow = blockIdx.y * 128;
    int bcol = blockIdx.x * 128;

    float acc[4][16];
#pragma unroll
    for (int i = 0; i < 4; i++)
#pragma unroll
        for (int j = 0; j < 16; j++) acc[i][j] = 0.f;

    const int NC = K / TK;
    auto load_stage = [&](int i) {
        int kc = i * TK;
        uint32_t st = sb + (uint32_t)(i % 3) * STAGE_BYTES;
#pragma unroll
        for (int c = 0; c < 2; c++) {
            int idx = tid + 256 * c;
            int row = idx >> 2, q = idx & 3;
            uint32_t soff = (uint32_t)(row * SM_STRIDE + q * 16);
            size_t gA = (size_t)(brow + row) * K + kc + q * 8;
            size_t gB = (size_t)(bcol + row) * K + kc + q * 8;
            cp_async16(st + soff,                 Ahi + gA);
            cp_async16(st + MAT_BYTES + soff,     Alo + gA);
            cp_async16(st + 2 * MAT_BYTES + soff, Bhi + gB);
            cp_async16(st + 3 * MAT_BYTES + soff, Blo + gB);
        }
        asm volatile("cp.async.commit_group;");
    };

    int grp = lane >> 3, l7 = lane & 7;
    uint32_t aOff = (uint32_t)((wm * 64 + (grp & 1) * 8 + l7) * SM_STRIDE + (grp >> 1) * 16);
    uint32_t bOff = (uint32_t)((wn * 32 + (grp >> 1) * 8 + l7) * SM_STRIDE + (grp & 1) * 16);

    load_stage(0);
    load_stage(1);
    for (int i = 0; i < NC; i++) {
        if (i < NC - 1) asm volatile("cp.async.wait_group 1;");
        else            asm volatile("cp.async.wait_group 0;");
        __syncthreads();
        if (i + 2 < NC) load_stage(i + 2);
        uint32_t st = sb + (uint32_t)(i % 3) * STAGE_BYTES;
#pragma unroll
        for (int ks = 0; ks < 2; ks++) {
            uint32_t ah[4][4], al[4][4], bh[2][4], bl[2][4];
#pragma unroll
            for (int mt = 0; mt < 4; mt++) {
                uint32_t a = st + aOff + (uint32_t)(mt * 16 * SM_STRIDE + ks * 32);
                ldm_x4(ah[mt], a);
                ldm_x4(al[mt], a + MAT_BYTES);
            }
#pragma unroll
            for (int np = 0; np < 2; np++) {
                uint32_t b = st + 2 * MAT_BYTES + bOff + (uint32_t)(np * 16 * SM_STRIDE + ks * 32);
                ldm_x4(bh[np], b);
                ldm_x4(bl[np], b + MAT_BYTES);
            }
#pragma unroll
            for (int mt = 0; mt < 4; mt++)
#pragma unroll
                for (int nt = 0; nt < 4; nt++) {
                    float* cc = &acc[mt][nt * 4];
                    const uint32_t* bhf = &bh[nt >> 1][(nt & 1) * 2];
                    const uint32_t* blf = &bl[nt >> 1][(nt & 1) * 2];
                    mma16816(cc, ah[mt], bhf);
                    mma16816(cc, al[mt], bhf);
                    mma16816(cc, ah[mt], blf);
                }
        }
    }

    // epilogue: bias + leaky, store, and fused BN partial stats
    int b = brow >> 11;   // 2048 rows per graph
    int r0base = brow + wm * 64 + (lane >> 2);
    int cbase  = bcol + wn * 32 + (lane & 3) * 2;
    float s0[4], q0[4], s1[4], q1[4];
#pragma unroll
    for (int nt = 0; nt < 4; nt++) { s0[nt] = q0[nt] = s1[nt] = q1[nt] = 0.f; }
#pragma unroll
    for (int mt = 0; mt < 4; mt++) {
#pragma unroll
        for (int nt = 0; nt < 4; nt++) {
            int c  = cbase + nt * 8;
            float2 bz = *(const float2*)(bias + c);
            float* a4 = &acc[mt][nt * 4];
            float v0 = a4[0] + bz.x, v1 = a4[1] + bz.y;
            float v2 = a4[2] + bz.x, v3 = a4[3] + bz.y;
            v0 = (v0 > 0.f) ? v0 : 0.01f * v0;
            v1 = (v1 > 0.f) ? v1 : 0.01f * v1;
            v2 = (v2 > 0.f) ? v2 : 0.01f * v2;
            v3 = (v3 > 0.f) ? v3 : 0.01f * v3;
            int r0 = r0base + mt * 16;
            *(float2*)(C + (size_t)r0 * O + c)       = make_float2(v0, v1);
            *(float2*)(C + (size_t)(r0 + 8) * O + c) = make_float2(v2, v3);
            s0[nt] += v0 + v2;  q0[nt] += v0 * v0 + v2 * v2;
            s1[nt] += v1 + v3;  q1[nt] += v1 * v1 + v3 * v3;
        }
    }
#pragma unroll
    for (int nt = 0; nt < 4; nt++) {
        float a = s0[nt], bq = q0[nt], cs = s1[nt], dq = q1[nt];
#pragma unroll
        for (int m = 4; m <= 16; m <<= 1) {
            a  += __shfl_xor_sync(0xffffffffu, a,  m);
            bq += __shfl_xor_sync(0xffffffffu, bq, m);
            cs += __shfl_xor_sync(0xffffffffu, cs, m);
            dq += __shfl_xor_sync(0xffffffffu, dq, m);
        }
        if (lane < 4) {
            int c = cbase + nt * 8;
            atomicAdd(&g_sum[b * FMAX + c],      a);
            atomicAdd(&g_sum2[b * FMAX + c],     bq);
            atomicAdd(&g_sum[b * FMAX + c + 1],  cs);
            atomicAdd(&g_sum2[b * FMAX + c + 1], dq);
        }
    }
}

// ==================== BN stats finalize ====================
__global__ void stats_final_kernel(const float* __restrict__ g, const float* __restrict__ be, int O) {
    int b = blockIdx.y;
    int o = blockIdx.x * 256 + threadIdx.x;
    float mu  = g_sum[b * FMAX + o] * (1.0f / NNODES);
    float var = g_sum2[b * FMAX + o] * (1.0f / NNODES) - mu * mu;
    if (var < 0.f) var = 0.f;
    float a = g[o] * rsqrtf(var + BN_EPS);
    g_alpha[b * O + o] = a;
    g_beta[b * O + o]  = be[o] - mu * a;
}

// ==================== final: BN apply + LayerNorm ====================
__global__ void final_kernel(const float* __restrict__ T, const float* __restrict__ ln_g,
                             const float* __restrict__ ln_b, float* __restrict__ out) {
    const int O = 1024;
    int b = blockIdx.y, n = blockIdx.x, t = threadIdx.x;
    size_t rowbase = ((size_t)b * NNODES + n) * O;
    float4 tv = ((const float4*)(T + rowbase))[t];
    float4 av = ((const float4*)g_alpha)[b * (O / 4) + t];
    float4 cv = ((const float4*)g_beta)[b * (O / 4) + t];
    float4 v;
    v.x = tv.x * av.x + cv.x; v.y = tv.y * av.y + cv.y;
    v.z = tv.z * av.z + cv.z; v.w = tv.w * av.w + cv.w;

    float s  = v.x + v.y + v.z + v.w;
    float s2 = v.x * v.x + v.y * v.y + v.z * v.z + v.w * v.w;
#pragma unroll
    for (int off = 16; off > 0; off >>= 1) {
        s  += __shfl_xor_sync(0xffffffffu, s, off);
        s2 += __shfl_xor_sync(0xffffffffu, s2, off);
    }
    __shared__ float ss[8], ss2[8];
    __shared__ float mu_s, r_s;
    int warp = t >> 5, lane = t & 31;
    if (lane == 0) { ss[warp] = s; ss2[warp] = s2; }
    __syncthreads();
    if (t == 0) {
        float S = 0.f, S2 = 0.f;
        for (int i = 0; i < 8; i++) { S += ss[i]; S2 += ss2[i]; }
        float mu  = S * (1.0f / O);
        float var = S2 * (1.0f / O) - mu * mu;
        if (var < 0.f) var = 0.f;
        mu_s = mu;
        r_s  = rsqrtf(var + BN_EPS);
    }
    __syncthreads();
    float mu = mu_s, r = r_s;
    float4 g4 = ((const float4*)ln_g)[t];
    float4 b4 = ((const float4*)ln_b)[t];
    float4 o;
    o.x = (v.x - mu) * r * g4.x + b4.x;
    o.y = (v.y - mu) * r * g4.y + b4.y;
    o.z = (v.z - mu) * r * g4.z + b4.z;
    o.w = (v.w - mu) * r * g4.w + b4.w;
    ((float4*)(out + rowbase))[t] = o;
}

// ==================== host ====================
static void launch_agg(int F, bool bn, const float* Hc, __nv_bfloat16* Phi, __nv_bfloat16* Plo) {
    if (F == 64)        agg_kernel<64, false>  <<<dim3(NNODES / 16, NB), dim3(16, 16)>>>(Hc, Phi, Plo);
    else if (F == 256)  agg_kernel<256, true>  <<<dim3(NNODES / 4,  NB), dim3(64, 4)>>>(Hc, Phi, Plo);
    else if (F == 512)  agg_kernel<512, true>  <<<dim3(NNODES / 2,  NB), dim3(128, 2)>>>(Hc, Phi, Plo);
    else                agg_kernel<1024, true> <<<dim3(NNODES,      NB), dim3(256, 1)>>>(Hc, Phi, Plo);
}

extern "C" void kernel_launch(void* const* d_in, const int* in_sizes, int n_in,
                              void* d_out, int out_size) {
    const float *x, *w[5], *bb[5], *gg[5], *be[5], *lng, *lnb;
    const void* edges;
    if (in_sizes[0] == 16384) {
        for (int i = 0; i < 5; i++) {
            w[i]  = (const float*)d_in[4 * i + 0];
            bb[i] = (const float*)d_in[4 * i + 1];
            gg[i] = (const float*)d_in[4 * i + 2];
            be[i] = (const float*)d_in[4 * i + 3];
        }
        lng = (const float*)d_in[20];
        lnb = (const float*)d_in[21];
        x   = (const float*)d_in[22];
        edges = d_in[23];
    } else {
        x     = (const float*)d_in[0];
        edges = d_in[1];
        for (int i = 0; i < 5; i++) {
            w[i]  = (const float*)d_in[2 + 4 * i + 0];
            bb[i] = (const float*)d_in[2 + 4 * i + 1];
            gg[i] = (const float*)d_in[2 + 4 * i + 2];
            be[i] = (const float*)d_in[2 + 4 * i + 3];
        }
        lng = (const float*)d_in[22];
        lnb = (const float*)d_in[23];
    }

    static int smem_set = 0;
    if (!smem_set) {
        cudaFuncSetAttribute(mma_gemm_kernel, cudaFuncAttributeMaxDynamicSharedMemorySize, GEMM_SMEM);
        smem_set = 1;
    }

    __nv_bfloat16 *Phi, *Plo, *Whi, *Wlo;
    float* T;
    cudaGetSymbolAddress((void**)&Phi, g_Phi);
    cudaGetSymbolAddress((void**)&Plo, g_Plo);
    cudaGetSymbolAddress((void**)&Whi, g_Whi);
    cudaGetSymbolAddress((void**)&Wlo, g_Wlo);
    cudaGetSymbolAddress((void**)&T,   g_T);

    convert_all_w_kernel<<<(692224 + 255) / 256, 256>>>(w[0], w[1], w[2], w[3], w[4]);
    detect_kernel<<<1, 32>>>(edges);
    zero_deg_kernel<<<8, 256>>>();
    count_deg_kernel<<<NEDGES / 256, 256>>>(edges);
    dinv_kernel<<<8, 256>>>();
    scan_kernel<<<1, 1024>>>();
    fill_kernel<<<NEDGES / 256, 256>>>(edges);

    const int din[5]  = {64, 256, 512, 1024, 1024};
    const int dout[5] = {256, 512, 1024, 1024, 1024};
    const int woff[5] = {0, 16384, 147456, 671744, 1720320};
    const float* Hc = x;
    for (int l = 0; l < 5; l++) {
        int K = din[l], O = dout[l];
        launch_agg(K, l > 0, Hc, Phi, Plo);
        mma_gemm_kernel<<<dim3(O / 128, NROWS / 128), 256, GEMM_SMEM>>>(
            Phi, Plo, Whi + woff[l], Wlo + woff[l], bb[l], T, K, O);
        stats_final_kernel<<<dim3(O / 256, NB), 256>>>(gg[l], be[l], O);
        if (l == 4) final_kernel<<<dim3(NNODES, NB), 256>>>(T, lng, lnb, (float*)d_out);
        Hc = T;
    }
}

// round 5
// speedup vs baseline: 2.3576x; 1.0300x over previous
#include <cuda_runtime.h>
#include <cuda_bf16.h>
#include <cuda_fp16.h>
#include <cstdint>
#include <math.h>

#define NNODES 2048
#define NEDGES 65536
#define NB     8
#define FMAX   1024
#define NROWS  (NB * NNODES)   // 16384
#define BN_EPS 1e-5f

// ==================== device scratch ====================
__device__ int   g_is64;
__device__ int   g_deg[NNODES];
__device__ float g_dinv[NNODES];
__device__ int   g_off[NNODES + 1];
__device__ int   g_cursor[NNODES];
__device__ int   g_csr_src[NEDGES];
__device__ float g_csr_norm[NEDGES];
__device__ float g_alpha[NB * FMAX];
__device__ float g_beta[NB * FMAX];
__device__ float g_sum[NB * FMAX];    // indexed b*FMAX + o
__device__ float g_sum2[NB * FMAX];
__device__ __align__(16) __nv_bfloat16 g_Phi[(size_t)NROWS * FMAX];
__device__ __align__(16) __nv_bfloat16 g_Plo[(size_t)NROWS * FMAX];
#define WTOTAL 2768896   // sum of all 5 weight matrices
__device__ __align__(16) __nv_bfloat16 g_Whi[WTOTAL];
__device__ __align__(16) __nv_bfloat16 g_Wlo[WTOTAL];
__device__ __align__(16) float  g_T[(size_t)NROWS * FMAX];    // layer-5 output (fp32, for LN)
__device__ __align__(16) __half g_T16[(size_t)NROWS * FMAX];  // layers 1-4 hidden state (fp16)

// ==================== graph preprocessing ====================
__global__ void detect_kernel(const void* edges) {
    if (threadIdx.x == 0) {
        const long long* p = (const long long*)edges;
        int is64 = 1;
        for (int i = 0; i < 16; i++) {
            long long v = p[i];
            if (v < 0 || v >= NNODES) is64 = 0;
        }
        g_is64 = is64;
    }
}
__device__ __forceinline__ int edge_val(const void* edges, int idx) {
    if (g_is64) return (int)((const long long*)edges)[idx];
    return ((const int*)edges)[idx];
}
__global__ void zero_deg_kernel() {
    int i = blockIdx.x * blockDim.x + threadIdx.x;
    if (i < NNODES) g_deg[i] = 0;
}
__global__ void count_deg_kernel(const void* edges) {
    int e = blockIdx.x * blockDim.x + threadIdx.x;
    if (e < NEDGES) atomicAdd(&g_deg[edge_val(edges, NEDGES + e)], 1);
}
__global__ void dinv_kernel() {
    int i = blockIdx.x * blockDim.x + threadIdx.x;
    if (i < NNODES) g_dinv[i] = rsqrtf((float)(g_deg[i] + 1));
}
__global__ void scan_kernel() {
    __shared__ int part[1024];
    int t = threadIdx.x;
    int c0 = g_deg[2 * t];
    int c1 = g_deg[2 * t + 1];
    part[t] = c0 + c1;
    __syncthreads();
    for (int off = 1; off < 1024; off <<= 1) {
        int v = (t >= off) ? part[t - off] : 0;
        __syncthreads();
        part[t] += v;
        __syncthreads();
    }
    int base = (t > 0) ? part[t - 1] : 0;
    g_off[2 * t] = base;        g_off[2 * t + 1] = base + c0;
    g_cursor[2 * t] = base;     g_cursor[2 * t + 1] = base + c0;
    if (t == 1023) g_off[2048] = part[1023];
}
__global__ void fill_kernel(const void* edges) {
    int e = blockIdx.x * blockDim.x + threadIdx.x;
    if (e < NEDGES) {
        int s = edge_val(edges, e);
        int d = edge_val(edges, NEDGES + e);
        int p = atomicAdd(&g_cursor[d], 1);
        g_csr_src[p]  = s;
        g_csr_norm[p] = g_dinv[s] * g_dinv[d];
    }
}

// ==================== weight conversion (all 5 layers, one launch) ====================
__device__ __forceinline__ uint32_t pack2(float a, float b) {
    __nv_bfloat162 p;
    p.x = __float2bfloat16(a); p.y = __float2bfloat16(b);
    return *(uint32_t*)&p;
}
__constant__ int c_woff4[6] = {0, 4096, 36864, 167936, 430080, 692224}; // float4 units
__global__ void convert_all_w_kernel(const float* __restrict__ w1, const float* __restrict__ w2,
                                     const float* __restrict__ w3, const float* __restrict__ w4,
                                     const float* __restrict__ w5) {
    int i = blockIdx.x * blockDim.x + threadIdx.x;
    if (i >= 692224) return;
    const float* src;
    int local;
    if (i < c_woff4[1])      { src = w1; local = i; }
    else if (i < c_woff4[2]) { src = w2; local = i - c_woff4[1]; }
    else if (i < c_woff4[3]) { src = w3; local = i - c_woff4[2]; }
    else if (i < c_woff4[4]) { src = w4; local = i - c_woff4[3]; }
    else                     { src = w5; local = i - c_woff4[4]; }
    float4 v = ((const float4*)src)[local];
    float hx = __bfloat162float(__float2bfloat16(v.x));
    float hy = __bfloat162float(__float2bfloat16(v.y));
    float hz = __bfloat162float(__float2bfloat16(v.z));
    float hw = __bfloat162float(__float2bfloat16(v.w));
    ((uint2*)g_Whi)[i] = make_uint2(pack2(v.x, v.y), pack2(v.z, v.w));
    ((uint2*)g_Wlo)[i] = make_uint2(pack2(v.x - hx, v.y - hy), pack2(v.z - hz, v.w - hw));
}

// ==================== aggregation (raw gather + deferred BN affine) -> hi/lo bf16 ====================
// group-of-4-features loaders (fp32 or fp16 storage)
__device__ __forceinline__ float4 load_h4(const float* H, size_t gidx) {
    return ((const float4*)H)[gidx];
}
__device__ __forceinline__ float4 load_h4(const __half* H, size_t gidx) {
    uint2 u = ((const uint2*)H)[gidx];
    float2 fa = __half22float2(*(__half2*)&u.x);
    float2 fb = __half22float2(*(__half2*)&u.y);
    return make_float4(fa.x, fa.y, fb.x, fb.y);
}

template <int F, bool BN, typename TIN>
__global__ void agg_kernel(const TIN* __restrict__ Hsrc,
                           __nv_bfloat16* __restrict__ Phi, __nv_bfloat16* __restrict__ Plo) {
    constexpr int F4 = F / 4;
    int b = blockIdx.y;
    // zero BN-stat accumulators for THIS layer's GEMM (runs before GEMM in-stream)
    if (blockIdx.x == 0) {
        int ft = threadIdx.y * blockDim.x + threadIdx.x;
        for (int i = ft; i < FMAX; i += 256) {
            g_sum[b * FMAX + i]  = 0.f;
            g_sum2[b * FMAX + i] = 0.f;
        }
    }
    int node = blockIdx.x * blockDim.y + threadIdx.y;
    int f4   = threadIdx.x;
    size_t gbase = (size_t)b * NNODES * F4;

    float wself = g_dinv[node] * g_dinv[node];
    float4 hv = load_h4(Hsrc, gbase + (size_t)node * F4 + f4);
    float4 acc = make_float4(wself * hv.x, wself * hv.y, wself * hv.z, wself * hv.w);
    float4 acc2 = make_float4(0.f, 0.f, 0.f, 0.f);
    float wsum = wself, wsum2 = 0.f;

    int beg = g_off[node], end = g_off[node + 1];
    int e = beg;
    for (; e + 2 <= end; e += 2) {
        int   s0 = g_csr_src[e],     s1 = g_csr_src[e + 1];
        float w0 = g_csr_norm[e],    w1 = g_csr_norm[e + 1];
        float4 h0 = load_h4(Hsrc, gbase + (size_t)s0 * F4 + f4);
        float4 h1 = load_h4(Hsrc, gbase + (size_t)s1 * F4 + f4);
        acc.x  += w0 * h0.x; acc.y  += w0 * h0.y; acc.z  += w0 * h0.z; acc.w  += w0 * h0.w;
        acc2.x += w1 * h1.x; acc2.y += w1 * h1.y; acc2.z += w1 * h1.z; acc2.w += w1 * h1.w;
        wsum += w0; wsum2 += w1;
    }
    if (e < end) {
        int   s = g_csr_src[e];
        float w = g_csr_norm[e];
        float4 h = load_h4(Hsrc, gbase + (size_t)s * F4 + f4);
        acc.x += w * h.x; acc.y += w * h.y; acc.z += w * h.z; acc.w += w * h.w;
        wsum += w;
    }
    acc.x += acc2.x; acc.y += acc2.y; acc.z += acc2.z; acc.w += acc2.w;
    wsum += wsum2;

    if (BN) {
        float4 al = ((const float4*)g_alpha)[b * F4 + f4];
        float4 bt = ((const float4*)g_beta)[b * F4 + f4];
        acc.x = acc.x * al.x + bt.x * wsum;
        acc.y = acc.y * al.y + bt.y * wsum;
        acc.z = acc.z * al.z + bt.z * wsum;
        acc.w = acc.w * al.w + bt.w * wsum;
    }
    float hx = __bfloat162float(__float2bfloat16(acc.x));
    float hy = __bfloat162float(__float2bfloat16(acc.y));
    float hz = __bfloat162float(__float2bfloat16(acc.z));
    float hw = __bfloat162float(__float2bfloat16(acc.w));
    size_t idx = ((size_t)b * NNODES + node) * F4 + f4;
    ((uint2*)Phi)[idx] = make_uint2(pack2(acc.x, acc.y), pack2(acc.z, acc.w));
    ((uint2*)Plo)[idx] = make_uint2(pack2(acc.x - hx, acc.y - hy), pack2(acc.z - hz, acc.w - hw));
}

// ==================== mma.sync GEMM (3-stage pipeline, fused BN stats) ====================
#define TK        32
#define SM_STRIDE 80
#define MAT_BYTES (128 * SM_STRIDE)       // 10240
#define STAGE_BYTES (4 * MAT_BYTES)       // 40960
#define GEMM_SMEM (3 * STAGE_BYTES)       // 122880

__device__ __forceinline__ void cp_async16(uint32_t saddr, const void* gptr) {
    asm volatile("cp.async.cg.shared.global [%0], [%1], 16;" :: "r"(saddr), "l"(gptr));
}
__device__ __forceinline__ void ldm_x4(uint32_t* r, uint32_t addr) {
    asm volatile("ldmatrix.sync.aligned.m8n8.x4.shared.b16 {%0,%1,%2,%3}, [%4];"
        : "=r"(r[0]), "=r"(r[1]), "=r"(r[2]), "=r"(r[3]) : "r"(addr));
}
__device__ __forceinline__ void mma16816(float* c, const uint32_t* a, const uint32_t* b) {
    asm volatile("mma.sync.aligned.m16n8k16.row.col.f32.bf16.bf16.f32 "
        "{%0,%1,%2,%3}, {%4,%5,%6,%7}, {%8,%9}, {%0,%1,%2,%3};"
        : "+f"(c[0]), "+f"(c[1]), "+f"(c[2]), "+f"(c[3])
        : "r"(a[0]), "r"(a[1]), "r"(a[2]), "r"(a[3]), "r"(b[0]), "r"(b[1]));
}
__device__ __forceinline__ uint32_t smem_u32(const void* p) {
    uint32_t a;
    asm("{ .reg .u64 t; cvta.to.shared.u64 t, %1; cvt.u32.u64 %0, t; }" : "=r"(a) : "l"(p));
    return a;
}

template <bool HALF_OUT>
__global__ __launch_bounds__(256, 1) void mma_gemm_kernel(
    const __nv_bfloat16* __restrict__ Ahi, const __nv_bfloat16* __restrict__ Alo,
    const __nv_bfloat16* __restrict__ Bhi, const __nv_bfloat16* __restrict__ Blo,
    const float* __restrict__ bias, void* __restrict__ Cout, int K, int O) {
    extern __shared__ __align__(16) char smem[];
    uint32_t sb = smem_u32(smem);
    int tid  = threadIdx.x;
    int lane = tid & 31, wid = tid >> 5;
    int wm = wid >> 2, wn = wid & 3;
    int brow = blockIdx.y * 128;
    int bcol = blockIdx.x * 128;

    float acc[4][16];
#pragma unroll
    for (int i = 0; i < 4; i++)
#pragma unroll
        for (int j = 0; j < 16; j++) acc[i][j] = 0.f;

    const int NC = K / TK;
    auto load_stage = [&](int i) {
        int kc = i * TK;
        uint32_t st = sb + (uint32_t)(i % 3) * STAGE_BYTES;
#pragma unroll
        for (int c = 0; c < 2; c++) {
            int idx = tid + 256 * c;
            int row = idx >> 2, q = idx & 3;
            uint32_t soff = (uint32_t)(row * SM_STRIDE + q * 16);
            size_t gA = (size_t)(brow + row) * K + kc + q * 8;
            size_t gB = (size_t)(bcol + row) * K + kc + q * 8;
            cp_async16(st + soff,                 Ahi + gA);
            cp_async16(st + MAT_BYTES + soff,     Alo + gA);
            cp_async16(st + 2 * MAT_BYTES + soff, Bhi + gB);
            cp_async16(st + 3 * MAT_BYTES + soff, Blo + gB);
        }
        asm volatile("cp.async.commit_group;");
    };

    int grp = lane >> 3, l7 = lane & 7;
    uint32_t aOff = (uint32_t)((wm * 64 + (grp & 1) * 8 + l7) * SM_STRIDE + (grp >> 1) * 16);
    uint32_t bOff = (uint32_t)((wn * 32 + (grp >> 1) * 8 + l7) * SM_STRIDE + (grp & 1) * 16);

    load_stage(0);
    load_stage(1);
    for (int i = 0; i < NC; i++) {
        if (i < NC - 1) asm volatile("cp.async.wait_group 1;");
        else            asm volatile("cp.async.wait_group 0;");
        __syncthreads();
        if (i + 2 < NC) load_stage(i + 2);
        uint32_t st = sb + (uint32_t)(i % 3) * STAGE_BYTES;
#pragma unroll
        for (int ks = 0; ks < 2; ks++) {
            uint32_t ah[4][4], al[4][4], bh[2][4], bl[2][4];
#pragma unroll
            for (int mt = 0; mt < 4; mt++) {
                uint32_t a = st + aOff + (uint32_t)(mt * 16 * SM_STRIDE + ks * 32);
                ldm_x4(ah[mt], a);
                ldm_x4(al[mt], a + MAT_BYTES);
            }
#pragma unroll
            for (int np = 0; np < 2; np++) {
                uint32_t b = st + 2 * MAT_BYTES + bOff + (uint32_t)(np * 16 * SM_STRIDE + ks * 32);
                ldm_x4(bh[np], b);
                ldm_x4(bl[np], b + MAT_BYTES);
            }
#pragma unroll
            for (int mt = 0; mt < 4; mt++)
#pragma unroll
                for (int nt = 0; nt < 4; nt++) {
                    float* cc = &acc[mt][nt * 4];
                    const uint32_t* bhf = &bh[nt >> 1][(nt & 1) * 2];
                    const uint32_t* blf = &bl[nt >> 1][(nt & 1) * 2];
                    mma16816(cc, ah[mt], bhf);
                    mma16816(cc, al[mt], bhf);
                    mma16816(cc, ah[mt], blf);
                }
        }
    }

    // epilogue: bias + leaky, store (fp16 or fp32), fused BN partial stats
    int b = brow >> 11;   // 2048 rows per graph
    int r0base = brow + wm * 64 + (lane >> 2);
    int cbase  = bcol + wn * 32 + (lane & 3) * 2;
    float s0[4], q0[4], s1[4], q1[4];
#pragma unroll
    for (int nt = 0; nt < 4; nt++) { s0[nt] = q0[nt] = s1[nt] = q1[nt] = 0.f; }
#pragma unroll
    for (int mt = 0; mt < 4; mt++) {
#pragma unroll
        for (int nt = 0; nt < 4; nt++) {
            int c  = cbase + nt * 8;
            float2 bz = *(const float2*)(bias + c);
            float* a4 = &acc[mt][nt * 4];
            float v0 = a4[0] + bz.x, v1 = a4[1] + bz.y;
            float v2 = a4[2] + bz.x, v3 = a4[3] + bz.y;
            v0 = (v0 > 0.f) ? v0 : 0.01f * v0;
            v1 = (v1 > 0.f) ? v1 : 0.01f * v1;
            v2 = (v2 > 0.f) ? v2 : 0.01f * v2;
            v3 = (v3 > 0.f) ? v3 : 0.01f * v3;
            int r0 = r0base + mt * 16;
            if (HALF_OUT) {
                __half* C16 = (__half*)Cout;
                *(__half2*)(C16 + (size_t)r0 * O + c)       = __floats2half2_rn(v0, v1);
                *(__half2*)(C16 + (size_t)(r0 + 8) * O + c) = __floats2half2_rn(v2, v3);
            } else {
                float* C = (float*)Cout;
                *(float2*)(C + (size_t)r0 * O + c)       = make_float2(v0, v1);
                *(float2*)(C + (size_t)(r0 + 8) * O + c) = make_float2(v2, v3);
            }
            s0[nt] += v0 + v2;  q0[nt] += v0 * v0 + v2 * v2;
            s1[nt] += v1 + v3;  q1[nt] += v1 * v1 + v3 * v3;
        }
    }
#pragma unroll
    for (int nt = 0; nt < 4; nt++) {
        float a = s0[nt], bq = q0[nt], cs = s1[nt], dq = q1[nt];
#pragma unroll
        for (int m = 4; m <= 16; m <<= 1) {
            a  += __shfl_xor_sync(0xffffffffu, a,  m);
            bq += __shfl_xor_sync(0xffffffffu, bq, m);
            cs += __shfl_xor_sync(0xffffffffu, cs, m);
            dq += __shfl_xor_sync(0xffffffffu, dq, m);
        }
        if (lane < 4) {
            int c = cbase + nt * 8;
            atomicAdd(&g_sum[b * FMAX + c],      a);
            atomicAdd(&g_sum2[b * FMAX + c],     bq);
            atomicAdd(&g_sum[b * FMAX + c + 1],  cs);
            atomicAdd(&g_sum2[b * FMAX + c + 1], dq);
        }
    }
}

// ==================== BN stats finalize ====================
__global__ void stats_final_kernel(const float* __restrict__ g, const float* __restrict__ be, int O) {
    int b = blockIdx.y;
    int o = blockIdx.x * 256 + threadIdx.x;
    float mu  = g_sum[b * FMAX + o] * (1.0f / NNODES);
    float var = g_sum2[b * FMAX + o] * (1.0f / NNODES) - mu * mu;
    if (var < 0.f) var = 0.f;
    float a = g[o] * rsqrtf(var + BN_EPS);
    g_alpha[b * O + o] = a;
    g_beta[b * O + o]  = be[o] - mu * a;
}

// ==================== final: BN apply + LayerNorm ====================
__global__ void final_kernel(const float* __restrict__ T, const float* __restrict__ ln_g,
                             const float* __restrict__ ln_b, float* __restrict__ out) {
    const int O = 1024;
    int b = blockIdx.y, n = blockIdx.x, t = threadIdx.x;
    size_t rowbase = ((size_t)b * NNODES + n) * O;
    float4 tv = ((const float4*)(T + rowbase))[t];
    float4 av = ((const float4*)g_alpha)[b * (O / 4) + t];
    float4 cv = ((const float4*)g_beta)[b * (O / 4) + t];
    float4 v;
    v.x = tv.x * av.x + cv.x; v.y = tv.y * av.y + cv.y;
    v.z = tv.z * av.z + cv.z; v.w = tv.w * av.w + cv.w;

    float s  = v.x + v.y + v.z + v.w;
    float s2 = v.x * v.x + v.y * v.y + v.z * v.z + v.w * v.w;
#pragma unroll
    for (int off = 16; off > 0; off >>= 1) {
        s  += __shfl_xor_sync(0xffffffffu, s, off);
        s2 += __shfl_xor_sync(0xffffffffu, s2, off);
    }
    __shared__ float ss[8], ss2[8];
    __shared__ float mu_s, r_s;
    int warp = t >> 5, lane = t & 31;
    if (lane == 0) { ss[warp] = s; ss2[warp] = s2; }
    __syncthreads();
    if (t == 0) {
        float S = 0.f, S2 = 0.f;
        for (int i = 0; i < 8; i++) { S += ss[i]; S2 += ss2[i]; }
        float mu  = S * (1.0f / O);
        float var = S2 * (1.0f / O) - mu * mu;
        if (var < 0.f) var = 0.f;
        mu_s = mu;
        r_s  = rsqrtf(var + BN_EPS);
    }
    __syncthreads();
    float mu = mu_s, r = r_s;
    float4 g4 = ((const float4*)ln_g)[t];
    float4 b4 = ((const float4*)ln_b)[t];
    float4 o;
    o.x = (v.x - mu) * r * g4.x + b4.x;
    o.y = (v.y - mu) * r * g4.y + b4.y;
    o.z = (v.z - mu) * r * g4.z + b4.z;
    o.w = (v.w - mu) * r * g4.w + b4.w;
    ((float4*)(out + rowbase))[t] = o;
}

// ==================== host ====================
extern "C" void kernel_launch(void* const* d_in, const int* in_sizes, int n_in,
                              void* d_out, int out_size) {
    const float *x, *w[5], *bb[5], *gg[5], *be[5], *lng, *lnb;
    const void* edges;
    if (in_sizes[0] == 16384) {
        for (int i = 0; i < 5; i++) {
            w[i]  = (const float*)d_in[4 * i + 0];
            bb[i] = (const float*)d_in[4 * i + 1];
            gg[i] = (const float*)d_in[4 * i + 2];
            be[i] = (const float*)d_in[4 * i + 3];
        }
        lng = (const float*)d_in[20];
        lnb = (const float*)d_in[21];
        x   = (const float*)d_in[22];
        edges = d_in[23];
    } else {
        x     = (const float*)d_in[0];
        edges = d_in[1];
        for (int i = 0; i < 5; i++) {
            w[i]  = (const float*)d_in[2 + 4 * i + 0];
            bb[i] = (const float*)d_in[2 + 4 * i + 1];
            gg[i] = (const float*)d_in[2 + 4 * i + 2];
            be[i] = (const float*)d_in[2 + 4 * i + 3];
        }
        lng = (const float*)d_in[22];
        lnb = (const float*)d_in[23];
    }

    static int smem_set = 0;
    if (!smem_set) {
        cudaFuncSetAttribute(mma_gemm_kernel<true>,  cudaFuncAttributeMaxDynamicSharedMemorySize, GEMM_SMEM);
        cudaFuncSetAttribute(mma_gemm_kernel<false>, cudaFuncAttributeMaxDynamicSharedMemorySize, GEMM_SMEM);
        smem_set = 1;
    }

    __nv_bfloat16 *Phi, *Plo, *Whi, *Wlo;
    float* T;
    __half* T16;
    cudaGetSymbolAddress((void**)&Phi, g_Phi);
    cudaGetSymbolAddress((void**)&Plo, g_Plo);
    cudaGetSymbolAddress((void**)&Whi, g_Whi);
    cudaGetSymbolAddress((void**)&Wlo, g_Wlo);
    cudaGetSymbolAddress((void**)&T,   g_T);
    cudaGetSymbolAddress((void**)&T16, g_T16);

    convert_all_w_kernel<<<(692224 + 255) / 256, 256>>>(w[0], w[1], w[2], w[3], w[4]);
    detect_kernel<<<1, 32>>>(edges);
    zero_deg_kernel<<<8, 256>>>();
    count_deg_kernel<<<NEDGES / 256, 256>>>(edges);
    dinv_kernel<<<8, 256>>>();
    scan_kernel<<<1, 1024>>>();
    fill_kernel<<<NEDGES / 256, 256>>>(edges);

    const int din[5]  = {64, 256, 512, 1024, 1024};
    const int dout[5] = {256, 512, 1024, 1024, 1024};
    const int woff[5] = {0, 16384, 147456, 671744, 1720320};
    for (int l = 0; l < 5; l++) {
        int K = din[l], O = dout[l];
        // aggregation (input: x fp32 for layer 0, fp16 hidden state after)
        if (l == 0)
            agg_kernel<64, false, float><<<dim3(NNODES / 16, NB), dim3(16, 16)>>>(x, Phi, Plo);
        else if (K == 256)
            agg_kernel<256, true, __half><<<dim3(NNODES / 4, NB), dim3(64, 4)>>>(T16, Phi, Plo);
        else if (K == 512)
            agg_kernel<512, true, __half><<<dim3(NNODES / 2, NB), dim3(128, 2)>>>(T16, Phi, Plo);
        else
            agg_kernel<1024, true, __half><<<dim3(NNODES, NB), dim3(256, 1)>>>(T16, Phi, Plo);
        // GEMM: layers 0-3 emit fp16 hidden state; layer 4 emits fp32 for LayerNorm
        if (l < 4)
            mma_gemm_kernel<true><<<dim3(O / 128, NROWS / 128), 256, GEMM_SMEM>>>(
                Phi, Plo, Whi + woff[l], Wlo + woff[l], bb[l], (void*)T16, K, O);
        else
            mma_gemm_kernel<false><<<dim3(O / 128, NROWS / 128), 256, GEMM_SMEM>>>(
                Phi, Plo, Whi + woff[l], Wlo + woff[l], bb[l], (void*)T, K, O);
        stats_final_kernel<<<dim3(O / 256, NB), 256>>>(gg[l], be[l], O);
        if (l == 4) final_kernel<<<dim3(NNODES, NB), 256>>>(T, lng, lnb, (float*)d_out);
    }
}